// round 14
// baseline (speedup 1.0000x reference)
#include <cuda_runtime.h>
#include <cuda_bf16.h>
#include <math.h>

#define NROWS 1048576
#define DTOT  64
#define DD    32
#define KK    40
#define BB    5.0f
#define NCELL 128
#define CELL_SCALE (NCELL / (2.0f * BB))   // 12.8

// ---------------------------------------------------------------------------
// Single fused kernel. Block builds spline tables in shared:
//   warp0: widths  -> bnd plane (probe) + t0.{x=cw, y=rbw}
//   warp1: heights -> t0.{z=ch, w=bh}
//   warp2: derivs  -> dd = {d0, d1} float2 plane
//   all threads:   128-cell uniform-grid LUT (u16, binary search)
// All tables [idx][dim]-transposed -> deterministic near-conflict-free LDS.
// Main loop: one warp per 4 rows/trip (8 batched LDGs -> high MLP);
// lane handles cols {lane, lane+32}; 4 LDS per transformed element.
// ---------------------------------------------------------------------------
__global__ __launch_bounds__(256, 5)
void rqs_forward_kernel(const float* __restrict__ u,
                        const float* __restrict__ w,
                        const float* __restrict__ h,
                        const float* __restrict__ dk,
                        const int*   __restrict__ nodes,
                        float* __restrict__ xout,
                        float* __restrict__ logd)
{
    __shared__ float          s_bndT[(KK + 1) * DD];  // cumw[k]; row40 = +INF (5.25 KB)
    __shared__ float4         s_t0T [KK * DD];         // {cw, rbw, ch, bh}    (20 KB)
    __shared__ float2         s_ddT [KK * DD];         // {d0, d1}             (10 KB)
    __shared__ unsigned short s_lutT[NCELL * DD];      // bin idx per cell     (8 KB)
    __shared__ int            s_inv [DTOT];

    const int tid  = threadIdx.x;
    const int lane = tid & 31;
    const int warp = tid >> 5;

    // ---- Phase A: build tables (3 warps in parallel, 1 dim per lane) ----
    if (tid < DTOT) s_inv[tid] = -1;

    if (warp == 0) {                       // widths -> cw (.x), rbw (.y), bnd
        const int j = lane;
        const float* row = w + j * KK;
        float mx = -1e30f;
        for (int k = 0; k < KK; k++) mx = fmaxf(mx, row[k]);
        float s = 0.f;
        for (int k = 0; k < KK; k++) s += __expf(row[k] - mx);
        const float inv_s = (2.0f * BB) / s;
        float cum = -BB;
        for (int k = 0; k < KK; k++) {
            s_bndT[k * DD + j]  = cum;
            s_t0T[k * DD + j].x = cum;
            const float wd = __expf(row[k] - mx) * inv_s;
            s_t0T[k * DD + j].y = 1.0f / wd;
            cum += wd;
        }
        s_bndT[KK * DD + j] = __int_as_float(0x7f800000);  // +INF probe sentinel
    } else if (warp == 1) {                // heights -> ch (.z), bh (.w)
        const int j = lane;
        const float* row = h + j * KK;
        float mx = -1e30f;
        for (int k = 0; k < KK; k++) mx = fmaxf(mx, row[k]);
        float s = 0.f;
        for (int k = 0; k < KK; k++) s += __expf(row[k] - mx);
        const float inv_s = (2.0f * BB) / s;
        float cum = -BB;
        for (int k = 0; k < KK; k++) {
            const float ht = __expf(row[k] - mx) * inv_s;
            s_t0T[k * DD + j].z = cum;
            s_t0T[k * DD + j].w = ht;
            cum += ht;
        }
    } else if (warp == 2) {                // derivatives -> dd = {d0, d1}
        const int j = lane;
        float prev = 1.0f;                 // derivs[0]
        const float* row = dk + j * (KK - 1);
        for (int k = 0; k < KK - 1; k++) {
            const float v  = row[k];
            const float sp = (v > 20.0f) ? v : log1pf(__expf(v));  // derivs[k+1]
            s_ddT[k * DD + j] = make_float2(prev, sp);
            prev = sp;
        }
        s_ddT[(KK - 1) * DD + j] = make_float2(prev, 1.0f);        // derivs[40]=1
    }
    __syncthreads();

    // ---- Phase B: LUT (all threads; i = c*32 + j matches [c][j] layout) ----
    for (int i = tid; i < NCELL * DD; i += 256) {
        const int j = i & (DD - 1);
        const int c = i >> 5;
        const float left = -BB + (float)c * (2.0f * BB / NCELL) - 1e-4f;
        int lo = 0, hi = KK;               // largest idx with bnd[idx] <= left
        #pragma unroll
        for (int it = 0; it < 6; it++) {
            const int mid = (lo + hi) >> 1;
            if (s_bndT[mid * DD + j] <= left) lo = mid; else hi = mid;
        }
        s_lutT[i] = (unsigned short)min(lo, KK - 1);
    }
    if (tid < DD) s_inv[nodes[tid]] = tid;
    __syncthreads();

    // ---- Main loop ----
    const int j0 = s_inv[lane];          // dim for col = lane (distinct per lane)
    const int j1 = s_inv[lane + 32];     // dim for col = lane + 32

    const unsigned gw     = blockIdx.x * 8 + warp;
    const unsigned stride = gridDim.x * 8 * 4;

    for (unsigned r0 = gw * 4; r0 < NROWS; r0 += stride)
    {
        const float* up = u + (size_t)r0 * DTOT;

        // batch all 8 loads up front (4 rows x 2 cols) for MLP
        float xA[4], xB[4];
        #pragma unroll
        for (int q = 0; q < 4; q++) {
            xA[q] = __ldcs(up + q * DTOT + lane);
            xB[q] = __ldcs(up + q * DTOT + lane + 32);
        }

        float acc[4];

        #pragma unroll
        for (int q = 0; q < 4; q++) {
            float a = 0.0f;   // log2-domain row accumulator (this lane's share)

            // ---- slot A: col = lane, dim j0 ----
            {
                const int   j = j0;
                const float x = xA[q];
                float y = x;
                if (j >= 0 && fabsf(x) <= BB) {
                    const int cell = min((int)fmaf(x, CELL_SCALE, BB * CELL_SCALE),
                                         NCELL - 1);
                    const int idx0 = (int)s_lutT[cell * DD + j];
                    const int idx  = idx0 +
                        ((s_bndT[(idx0 + 1) * DD + j] <= x) ? 1 : 0);

                    const float4 t0 = s_t0T[idx * DD + j];   // cw, rbw, ch, bh
                    const float2 dd = s_ddT[idx * DD + j];   // d0, d1

                    const float rbw = t0.y, bh = t0.w;
                    const float d0 = dd.x, d1 = dd.y;
                    const float delta = bh * rbw;
                    const float theta = (x - t0.x) * rbw;
                    const float omt   = 1.0f - theta;
                    const float t1m   = theta * omt;
                    const float denom = fmaf(d0 + d1 - 2.0f * delta, t1m, delta);
                    const float r     = __fdividef(1.0f, denom);
                    y = fmaf(bh * fmaf(delta * theta, theta, d0 * t1m), r, t0.z);
                    const float A = delta * delta *
                        (fmaf(d1 * theta, theta, 2.0f * delta * t1m) + d0 * omt * omt);
                    a += __log2f(A * r * r);
                }
                xA[q] = y;
            }
            // ---- slot B: col = lane + 32, dim j1 ----
            {
                const int   j = j1;
                const float x = xB[q];
                float y = x;
                if (j >= 0 && fabsf(x) <= BB) {
                    const int cell = min((int)fmaf(x, CELL_SCALE, BB * CELL_SCALE),
                                         NCELL - 1);
                    const int idx0 = (int)s_lutT[cell * DD + j];
                    const int idx  = idx0 +
                        ((s_bndT[(idx0 + 1) * DD + j] <= x) ? 1 : 0);

                    const float4 t0 = s_t0T[idx * DD + j];
                    const float2 dd = s_ddT[idx * DD + j];

                    const float rbw = t0.y, bh = t0.w;
                    const float d0 = dd.x, d1 = dd.y;
                    const float delta = bh * rbw;
                    const float theta = (x - t0.x) * rbw;
                    const float omt   = 1.0f - theta;
                    const float t1m   = theta * omt;
                    const float denom = fmaf(d0 + d1 - 2.0f * delta, t1m, delta);
                    const float r     = __fdividef(1.0f, denom);
                    y = fmaf(bh * fmaf(delta * theta, theta, d0 * t1m), r, t0.z);
                    const float A = delta * delta *
                        (fmaf(d1 * theta, theta, 2.0f * delta * t1m) + d0 * omt * omt);
                    a += __log2f(A * r * r);
                }
                xB[q] = y;
            }
            acc[q] = a;
        }

        // batched stores
        float* xp = xout + (size_t)r0 * DTOT;
        #pragma unroll
        for (int q = 0; q < 4; q++) {
            __stcs(xp + q * DTOT + lane,      xA[q]);
            __stcs(xp + q * DTOT + lane + 32, xB[q]);
        }

        // two paired warp reductions (6 SHFL each for 2 rows)
        #pragma unroll
        for (int p = 0; p < 2; p++) {
            float a0 = acc[2 * p], a1 = acc[2 * p + 1];
            a0 += __shfl_xor_sync(0xffffffffu, a0, 16);
            a1 += __shfl_xor_sync(0xffffffffu, a1, 16);
            float z = (lane < 16) ? a0 : a1;
            #pragma unroll
            for (int o = 8; o > 0; o >>= 1)
                z += __shfl_xor_sync(0xffffffffu, z, o);
            if ((lane & 15) == 0)
                __stcs(logd + r0 + 2 * p + (lane >> 4), z * 0.69314718056f);
        }
    }
}

extern "C" void kernel_launch(void* const* d_in, const int* in_sizes, int n_in,
                              void* d_out, int out_size)
{
    const float* u     = (const float*)d_in[0];
    const float* w     = (const float*)d_in[1];
    const float* h     = (const float*)d_in[2];
    const float* dk    = (const float*)d_in[3];
    const int*   nodes = (const int*)  d_in[4];

    float* xout = (float*)d_out;
    float* logd = xout + (size_t)NROWS * DTOT;

    rqs_forward_kernel<<<740, 256>>>(u, w, h, dk, nodes, xout, logd);
}

// round 16
// speedup vs baseline: 1.0875x; 1.0875x over previous
#include <cuda_runtime.h>
#include <cuda_bf16.h>
#include <math.h>

#define NROWS 1048576
#define DTOT  64
#define DD    32
#define KK    40
#define BB    5.0f
#define NCELL 128
#define CELL_SCALE (NCELL / (2.0f * BB))   // 12.8
#define RPT   8                            // rows per warp trip

// ---------------------------------------------------------------------------
// Single fused kernel. Each block builds the (tiny) spline tables in shared:
//   warp0: widths (softmax->cumsum->rbw + boundaries)
//   warp1: heights (ch, bh)
//   warp2: derivatives (softplus) -> d0 plane (.w of t0) + separate d1 plane
//   then all 256 threads: 128-cell uniform-grid LUT (binary search)
// Tables are [idx][dim]-transposed -> all gathers bank-conflict-free.
// Main loop: one warp per 8 rows/trip (16 batched LDGs -> 2KB in flight/warp);
// lane handles cols {lane, lane+32} of each row.
// ---------------------------------------------------------------------------
__global__ __launch_bounds__(256, 4)
void rqs_forward_kernel(const float* __restrict__ u,
                        const float* __restrict__ w,
                        const float* __restrict__ h,
                        const float* __restrict__ dk,
                        const int*   __restrict__ nodes,
                        float* __restrict__ xout,
                        float* __restrict__ logd)
{
    __shared__ float         s_bndT[(KK + 1) * DD];   // cumw[k]; row40 = +INF  (5.25 KB)
    __shared__ float4        s_t0T [KK * DD];          // {rbw, ch, bh, d0}     (20 KB)
    __shared__ float         s_d1T [KK * DD];          // d1 = derivs[k+1]      (5 KB)
    __shared__ unsigned char s_lutT[NCELL * DD];       // 4 KB
    __shared__ int           s_inv [DTOT];

    const int tid  = threadIdx.x;
    const int lane = tid & 31;
    const int warp = tid >> 5;

    // ---- Phase A: build tables (3 warps in parallel, 1 dim per lane) ----
    if (tid < DTOT) s_inv[tid] = -1;

    if (warp == 0) {                       // widths -> rbw (.x), boundaries
        const int j = lane;
        const float* row = w + j * KK;
        float mx = -1e30f;
        for (int k = 0; k < KK; k++) mx = fmaxf(mx, row[k]);
        float s = 0.f;
        for (int k = 0; k < KK; k++) s += __expf(row[k] - mx);
        const float inv_s = (2.0f * BB) / s;
        float cum = -BB;
        for (int k = 0; k < KK; k++) {
            s_bndT[k * DD + j] = cum;
            const float wd = __expf(row[k] - mx) * inv_s;
            s_t0T[k * DD + j].x = 1.0f / wd;
            cum += wd;
        }
        s_bndT[KK * DD + j] = __int_as_float(0x7f800000);  // +INF probe sentinel
    } else if (warp == 1) {                // heights -> ch (.y), bh (.z)
        const int j = lane;
        const float* row = h + j * KK;
        float mx = -1e30f;
        for (int k = 0; k < KK; k++) mx = fmaxf(mx, row[k]);
        float s = 0.f;
        for (int k = 0; k < KK; k++) s += __expf(row[k] - mx);
        const float inv_s = (2.0f * BB) / s;
        float cum = -BB;
        for (int k = 0; k < KK; k++) {
            const float ht = __expf(row[k] - mx) * inv_s;
            s_t0T[k * DD + j].y = cum;
            s_t0T[k * DD + j].z = ht;
            cum += ht;
        }
    } else if (warp == 2) {                // derivatives: d0 plane + d1 plane
        const int j = lane;
        s_t0T[0 * DD + j].w        = 1.0f;   // derivs[0]
        s_d1T[(KK - 1) * DD + j]   = 1.0f;   // derivs[40]
        const float* row = dk + j * (KK - 1);
        for (int k = 0; k < KK - 1; k++) {
            const float v  = row[k];
            const float sp = (v > 20.0f) ? v : log1pf(__expf(v));  // derivs[k+1]
            s_t0T[(k + 1) * DD + j].w = sp;   // d0 for bin k+1
            s_d1T[k * DD + j]         = sp;   // d1 for bin k
        }
    }
    __syncthreads();

    // ---- Phase B: LUT (all threads; i = c*32 + j matches [c][j] layout) ----
    for (int i = tid; i < NCELL * DD; i += 256) {
        const int j = i & (DD - 1);
        const int c = i >> 5;
        const float left = -BB + (float)c * (2.0f * BB / NCELL) - 1e-4f;
        int lo = 0, hi = KK;               // largest idx with bnd[idx] <= left
        #pragma unroll
        for (int it = 0; it < 6; it++) {
            const int mid = (lo + hi) >> 1;
            if (s_bndT[mid * DD + j] <= left) lo = mid; else hi = mid;
        }
        s_lutT[i] = (unsigned char)min(lo, KK - 1);
    }
    if (tid < DD) s_inv[nodes[tid]] = tid;
    __syncthreads();

    // ---- Main loop ----
    const int j0 = s_inv[lane];          // dim for col = lane (distinct per lane)
    const int j1 = s_inv[lane + 32];     // dim for col = lane + 32

    const unsigned gw     = blockIdx.x * 8 + warp;
    const unsigned stride = gridDim.x * 8 * RPT;

    for (unsigned r0 = gw * RPT; r0 < NROWS; r0 += stride)
    {
        const float* up = u + (size_t)r0 * DTOT;

        // batch all 16 loads up front (8 rows x 2 cols) for MLP
        float xA[RPT], xB[RPT];
        #pragma unroll
        for (int q = 0; q < RPT; q++) {
            xA[q] = __ldcs(up + q * DTOT + lane);
            xB[q] = __ldcs(up + q * DTOT + lane + 32);
        }

        float acc[RPT];

        #pragma unroll
        for (int q = 0; q < RPT; q++) {
            float a = 0.0f;   // log2-domain row accumulator (this lane's share)

            // ---- slot A: col = lane, dim j0 ----
            {
                const int   j = j0;
                const float x = xA[q];
                float y = x;
                if (j >= 0 && fabsf(x) <= BB) {
                    const int cell = min((int)fmaf(x, CELL_SCALE, BB * CELL_SCALE),
                                         NCELL - 1);
                    const int idx0 = (int)s_lutT[cell * DD + j];
                    const float b0 = s_bndT[idx0 * DD + j];
                    const float b1 = s_bndT[(idx0 + 1) * DD + j];
                    const bool  adv = (b1 <= x);
                    const int   idx = idx0 + (adv ? 1 : 0);
                    const float cw  = adv ? b1 : b0;

                    const float4 t0 = s_t0T[idx * DD + j];   // rbw, ch, bh, d0
                    const float  d1 = s_d1T[idx * DD + j];

                    const float rbw = t0.x, bh = t0.z, d0 = t0.w;
                    const float delta = bh * rbw;
                    const float theta = (x - cw) * rbw;
                    const float omt   = 1.0f - theta;
                    const float t1m   = theta * omt;
                    const float denom = fmaf(d0 + d1 - 2.0f * delta, t1m, delta);
                    const float r     = __fdividef(1.0f, denom);
                    y = fmaf(bh * fmaf(delta * theta, theta, d0 * t1m), r, t0.y);
                    const float A = delta * delta *
                        (fmaf(d1 * theta, theta, 2.0f * delta * t1m) + d0 * omt * omt);
                    a += __log2f(A * r * r);
                }
                xA[q] = y;
            }
            // ---- slot B: col = lane + 32, dim j1 ----
            {
                const int   j = j1;
                const float x = xB[q];
                float y = x;
                if (j >= 0 && fabsf(x) <= BB) {
                    const int cell = min((int)fmaf(x, CELL_SCALE, BB * CELL_SCALE),
                                         NCELL - 1);
                    const int idx0 = (int)s_lutT[cell * DD + j];
                    const float b0 = s_bndT[idx0 * DD + j];
                    const float b1 = s_bndT[(idx0 + 1) * DD + j];
                    const bool  adv = (b1 <= x);
                    const int   idx = idx0 + (adv ? 1 : 0);
                    const float cw  = adv ? b1 : b0;

                    const float4 t0 = s_t0T[idx * DD + j];
                    const float  d1 = s_d1T[idx * DD + j];

                    const float rbw = t0.x, bh = t0.z, d0 = t0.w;
                    const float delta = bh * rbw;
                    const float theta = (x - cw) * rbw;
                    const float omt   = 1.0f - theta;
                    const float t1m   = theta * omt;
                    const float denom = fmaf(d0 + d1 - 2.0f * delta, t1m, delta);
                    const float r     = __fdividef(1.0f, denom);
                    y = fmaf(bh * fmaf(delta * theta, theta, d0 * t1m), r, t0.y);
                    const float A = delta * delta *
                        (fmaf(d1 * theta, theta, 2.0f * delta * t1m) + d0 * omt * omt);
                    a += __log2f(A * r * r);
                }
                xB[q] = y;
            }
            acc[q] = a;
        }

        // batched stores
        float* xp = xout + (size_t)r0 * DTOT;
        #pragma unroll
        for (int q = 0; q < RPT; q++) {
            __stcs(xp + q * DTOT + lane,      xA[q]);
            __stcs(xp + q * DTOT + lane + 32, xB[q]);
        }

        // four paired warp reductions (6 SHFL each for 2 rows)
        #pragma unroll
        for (int p = 0; p < RPT / 2; p++) {
            float a0 = acc[2 * p], a1 = acc[2 * p + 1];
            a0 += __shfl_xor_sync(0xffffffffu, a0, 16);
            a1 += __shfl_xor_sync(0xffffffffu, a1, 16);
            float z = (lane < 16) ? a0 : a1;
            #pragma unroll
            for (int o = 8; o > 0; o >>= 1)
                z += __shfl_xor_sync(0xffffffffu, z, o);
            if ((lane & 15) == 0)
                __stcs(logd + r0 + 2 * p + (lane >> 4), z * 0.69314718056f);
        }
    }
}

extern "C" void kernel_launch(void* const* d_in, const int* in_sizes, int n_in,
                              void* d_out, int out_size)
{
    const float* u     = (const float*)d_in[0];
    const float* w     = (const float*)d_in[1];
    const float* h     = (const float*)d_in[2];
    const float* dk    = (const float*)d_in[3];
    const int*   nodes = (const int*)  d_in[4];

    float* xout = (float*)d_out;
    float* logd = xout + (size_t)NROWS * DTOT;

    rqs_forward_kernel<<<592, 256>>>(u, w, h, dk, nodes, xout, logd);
}